// round 13
// baseline (speedup 1.0000x reference)
#include <cuda_runtime.h>
#include <cuda_fp16.h>

#define NN 100000
#define NE 1600000
#define HH 64
#define GG 64
#define EPS 1e-5f
#define NSB 98            // scan blocks = ceil(NN/1024)
#define NWARPS 25000      // agg: total warps; each handles 4 nodes strided

// ---------------- scratch (device globals; no allocations) ----------------
__device__ float g_hs[NN * HH];      // (X@W)*dinv fp32 (message source)
__device__ float g_a[NN * HH];       // activations a1 / a2
__device__ float g_dinv[NN];
__device__ int   g_hist[NN];         // zero-init; re-zeroed by scan each replay
__device__ int   g_rowptr[NN + 1];
__device__ int   g_cursor[NN];
__device__ int   g_perm[NE];
__device__ volatile int g_sstat[NSB];
__device__ volatile int g_sagg[NSB];
__device__ volatile int g_sinc[NSB];
__device__ float g_red1[128];        // BN1 stats (self-resetting via colstats)
__device__ float g_red2[128];        // BN2 stats (zeroed by scan)
__device__ int   g_ctr1;             // last-block counter (self-resetting)
__device__ float g_pscale[HH], g_pshift[HH];
__device__ float g_gsum[GG * HH];
__device__ int   g_gstart[GG + 1];

// ---------------- helpers ----------------
__device__ __forceinline__ float f2tf(float x) {
    unsigned y;
    asm("cvt.rna.tf32.f32 %0, %1;" : "=r"(y) : "f"(x));
    return __uint_as_float(y);
}
__device__ __forceinline__ void mma_tf32(float* d, const unsigned* a, const unsigned* b) {
    asm volatile(
        "mma.sync.aligned.m16n8k8.row.col.f32.tf32.tf32.f32 "
        "{%0,%1,%2,%3}, {%4,%5,%6,%7}, {%8,%9}, {%0,%1,%2,%3};\n"
        : "+f"(d[0]), "+f"(d[1]), "+f"(d[2]), "+f"(d[3])
        : "r"(a[0]), "r"(a[1]), "r"(a[2]), "r"(a[3]), "r"(b[0]), "r"(b[1]));
}

// ---------------- hist (+gstart search, +scan-flag reset) ----------------
__global__ void hist_kernel(const int4* __restrict__ dst4, const int* __restrict__ batch) {
    int e = blockIdx.x * 256 + threadIdx.x;
    if (blockIdx.x == 0) {
        if (threadIdx.x < NSB) g_sstat[threadIdx.x] = 0;
        if (threadIdx.x <= GG) {
            int g = threadIdx.x;
            int lo = 0, hi = NN;
            while (lo < hi) {
                int mid = (lo + hi) >> 1;
                if (batch[mid] < g) lo = mid + 1; else hi = mid;
            }
            g_gstart[g] = lo;
        }
    }
    if (e < NE / 4) {
        int4 d = dst4[e];
        atomicAdd(&g_hist[d.x], 1);
        atomicAdd(&g_hist[d.y], 1);
        atomicAdd(&g_hist[d.z], 1);
        atomicAdd(&g_hist[d.w], 1);
    }
}

// ---------------- single-pass scan (decoupled lookback) + dinv + zeroing ----------------
__global__ __launch_bounds__(1024) void scan_kernel() {
    __shared__ int sh[1024];
    __shared__ int s_excl;
    int t = threadIdx.x, b = blockIdx.x;
    int i = b * 1024 + t;
    int v = (i < NN) ? g_hist[i] : 0;
    if (i < NN) { g_dinv[i] = rsqrtf(1.0f + (float)v); g_hist[i] = 0; }
    if (b == 0 && t < 128) g_red2[t] = 0.f;
    sh[t] = v;
    __syncthreads();
    #pragma unroll
    for (int off = 1; off < 1024; off <<= 1) {
        int x = (t >= off) ? sh[t - off] : 0;
        __syncthreads();
        sh[t] += x;
        __syncthreads();
    }
    if (t == 0) {
        int total = sh[1023];
        if (b == 0) {
            g_sinc[0] = total; __threadfence(); g_sstat[0] = 2;
            s_excl = 0;
        } else {
            g_sagg[b] = total; __threadfence(); g_sstat[b] = 1;
            int ex = 0, j = b - 1;
            while (1) {
                int s;
                do { s = g_sstat[j]; } while (s == 0);
                if (s == 2) { ex += g_sinc[j]; break; }
                ex += g_sagg[j]; j--;
            }
            g_sinc[b] = ex + total; __threadfence(); g_sstat[b] = 2;
            s_excl = ex;
        }
    }
    __syncthreads();
    int excl = s_excl;
    if (i < NN) {
        int r = sh[t] - v + excl;
        g_rowptr[i] = r;
        g_cursor[i] = r;
    }
    if (i == 0) g_rowptr[NN] = NE;
}

__global__ void fill_kernel(const int4* __restrict__ src4, const int4* __restrict__ dst4) {
    int e = blockIdx.x * 256 + threadIdx.x;
    if (e < NE / 4) {
        int4 s = src4[e];
        int4 d = dst4[e];
        g_perm[atomicAdd(&g_cursor[d.x], 1)] = s.x;
        g_perm[atomicAdd(&g_cursor[d.y], 1)] = s.y;
        g_perm[atomicAdd(&g_cursor[d.z], 1)] = s.z;
        g_perm[atomicAdd(&g_cursor[d.w], 1)] = s.w;
    }
}

// ---------------- 3xTF32 GEMM, hi/lo split precomputed in smem ----------------
// Block tile 128x64, 8 warps (32x32 warp tile), K chunk 32, mma m16n8k8.
__global__ __launch_bounds__(256) void gemm_kernel(const float* __restrict__ Xext, int K,
                                                   const float* __restrict__ W, int use_bn) {
    __shared__ float Ah[128][36];
    __shared__ float Al[128][36];
    __shared__ float Bh[32][68];
    __shared__ float Bl[32][68];
    const float* X = Xext ? Xext : g_a;
    int t = threadIdx.x;
    int w = t >> 5, lane = t & 31;
    int g = lane >> 2, tg = lane & 3;
    int mr = (w & 3) * 32;
    int nc = (w >> 2) * 32;
    int row0 = blockIdx.x * 128;

    float acc[2][4][4];
    #pragma unroll
    for (int a = 0; a < 2; a++)
        #pragma unroll
        for (int b = 0; b < 4; b++)
            #pragma unroll
            for (int c = 0; c < 4; c++) acc[a][b][c] = 0.f;

    for (int k0 = 0; k0 < K; k0 += 32) {
        #pragma unroll
        for (int it = 0; it < 4; it++) {
            int idx = t + it * 256;
            int r = idx >> 3, k4 = (idx & 7) * 4;
            int gr = row0 + r;
            float4 v = make_float4(0.f, 0.f, 0.f, 0.f);
            if (gr < NN) {
                v = *(const float4*)&X[gr * K + k0 + k4];
                if (use_bn) {
                    int kb = k0 + k4;
                    v.x = v.x * g_pscale[kb + 0] + g_pshift[kb + 0];
                    v.y = v.y * g_pscale[kb + 1] + g_pshift[kb + 1];
                    v.z = v.z * g_pscale[kb + 2] + g_pshift[kb + 2];
                    v.w = v.w * g_pscale[kb + 3] + g_pshift[kb + 3];
                }
            }
            float4 h = make_float4(f2tf(v.x), f2tf(v.y), f2tf(v.z), f2tf(v.w));
            float4 l = make_float4(f2tf(v.x - h.x), f2tf(v.y - h.y),
                                   f2tf(v.z - h.z), f2tf(v.w - h.w));
            *(float4*)&Ah[r][k4] = h;
            *(float4*)&Al[r][k4] = l;
        }
        #pragma unroll
        for (int it = 0; it < 2; it++) {
            int idx = t + it * 256;
            int kk = idx >> 4, n4 = (idx & 15) * 4;
            float4 v = *(const float4*)&W[(k0 + kk) * 64 + n4];
            float4 h = make_float4(f2tf(v.x), f2tf(v.y), f2tf(v.z), f2tf(v.w));
            float4 l = make_float4(f2tf(v.x - h.x), f2tf(v.y - h.y),
                                   f2tf(v.z - h.z), f2tf(v.w - h.w));
            *(float4*)&Bh[kk][n4] = h;
            *(float4*)&Bl[kk][n4] = l;
        }
        __syncthreads();
        #pragma unroll
        for (int ks = 0; ks < 32; ks += 8) {
            unsigned ah[2][4], al[2][4], bh[4][2], bl[4][2];
            #pragma unroll
            for (int mt = 0; mt < 2; mt++) {
                int brow = mr + mt * 16;
                ah[mt][0] = __float_as_uint(Ah[brow + g][ks + tg]);
                ah[mt][1] = __float_as_uint(Ah[brow + g + 8][ks + tg]);
                ah[mt][2] = __float_as_uint(Ah[brow + g][ks + tg + 4]);
                ah[mt][3] = __float_as_uint(Ah[brow + g + 8][ks + tg + 4]);
                al[mt][0] = __float_as_uint(Al[brow + g][ks + tg]);
                al[mt][1] = __float_as_uint(Al[brow + g + 8][ks + tg]);
                al[mt][2] = __float_as_uint(Al[brow + g][ks + tg + 4]);
                al[mt][3] = __float_as_uint(Al[brow + g + 8][ks + tg + 4]);
            }
            #pragma unroll
            for (int nt = 0; nt < 4; nt++) {
                int col = nc + nt * 8 + g;
                bh[nt][0] = __float_as_uint(Bh[ks + tg][col]);
                bh[nt][1] = __float_as_uint(Bh[ks + tg + 4][col]);
                bl[nt][0] = __float_as_uint(Bl[ks + tg][col]);
                bl[nt][1] = __float_as_uint(Bl[ks + tg + 4][col]);
            }
            #pragma unroll
            for (int mt = 0; mt < 2; mt++)
                #pragma unroll
                for (int nt = 0; nt < 4; nt++) {
                    mma_tf32(acc[mt][nt], ah[mt], bl[nt]);
                    mma_tf32(acc[mt][nt], al[mt], bh[nt]);
                    mma_tf32(acc[mt][nt], ah[mt], bh[nt]);
                }
        }
        __syncthreads();
    }

    #pragma unroll
    for (int mt = 0; mt < 2; mt++) {
        int r0g = row0 + mr + mt * 16 + g;
        int r1g = r0g + 8;
        float dn0 = (r0g < NN) ? g_dinv[r0g] : 0.f;
        float dn1 = (r1g < NN) ? g_dinv[r1g] : 0.f;
        #pragma unroll
        for (int nt = 0; nt < 4; nt++) {
            int col = nc + nt * 8 + tg * 2;
            if (r0g < NN)
                *(float2*)&g_hs[r0g * 64 + col] =
                    make_float2(acc[mt][nt][0] * dn0, acc[mt][nt][1] * dn0);
            if (r1g < NN)
                *(float2*)&g_hs[r1g * 64 + col] =
                    make_float2(acc[mt][nt][2] * dn1, acc[mt][nt][3] * dn1);
        }
    }
}

// ---------------- aggregation: 4 nodes/warp, pipelined setup, 2 edges/LDG ----------------
// Warp W handles nodes {W, W+25000, W+50000, W+75000}; all rowptr loads and
// all 4 first-chunk perm loads are issued up-front so the per-node setup
// latency chains overlap. Lanes 0-15 gather even edges, 16-31 odd edges.
__global__ void agg_kernel(const float* __restrict__ bias) {
    int t = threadIdx.x;
    int w = t >> 5, lane = t & 31;
    int W = blockIdx.x * 8 + w;           // 3125 blocks x 8 warps = 25000 exactly
    int half = lane >> 4;                 // 0 or 1
    int l16 = lane & 15;
    const float4* h4 = (const float4*)g_hs;

    // issue all setup loads up-front
    int e_[4], end_[4], s0_[4];
    #pragma unroll
    for (int k = 0; k < 4; k++) {
        int n = W + k * NWARPS;
        e_[k] = g_rowptr[n];
        end_[k] = g_rowptr[n + 1];
    }
    #pragma unroll
    for (int k = 0; k < 4; k++) {
        int cnt = end_[k] - e_[k];
        if (cnt > 16) cnt = 16;
        int idx = (l16 < cnt) ? l16 : (cnt > 0 ? cnt - 1 : 0);
        int a = e_[k] + idx; if (a > NE - 1) a = NE - 1;
        s0_[k] = g_perm[a];
    }

    float dn_[4];
    #pragma unroll
    for (int k = 0; k < 4; k++) dn_[k] = g_dinv[W + k * NWARPS];
    float4 bb = ((const float4*)bias)[l16];

    #pragma unroll
    for (int k = 0; k < 4; k++) {
        int n = W + k * NWARPS;
        float4 acc = make_float4(0.f, 0.f, 0.f, 0.f);
        if (half == 0) acc = h4[n * 16 + l16];    // self term once
        int e = e_[k], end = end_[k];
        int s = s0_[k];
        while (e < end) {
            int cnt = end - e; if (cnt > 16) cnt = 16;
            int pairs = cnt >> 1;
            for (int j = 0; j < pairs; j++) {
                int si = __shfl_sync(0xffffffffu, s, 2 * j + half);
                float4 v = h4[si * 16 + l16];
                acc.x += v.x; acc.y += v.y; acc.z += v.z; acc.w += v.w;
            }
            if (cnt & 1) {
                int si = __shfl_sync(0xffffffffu, s, cnt - 1);
                if (half == 0) {
                    float4 v = h4[si * 16 + l16];
                    acc.x += v.x; acc.y += v.y; acc.z += v.z; acc.w += v.w;
                }
            }
            e += cnt;
            if (e < end) {                         // load next chunk's indices
                int c2 = end - e; if (c2 > 16) c2 = 16;
                int idx = (l16 < c2) ? l16 : c2 - 1;
                s = g_perm[e + idx];
            }
        }
        // combine halves
        acc.x += __shfl_xor_sync(0xffffffffu, acc.x, 16);
        acc.y += __shfl_xor_sync(0xffffffffu, acc.y, 16);
        acc.z += __shfl_xor_sync(0xffffffffu, acc.z, 16);
        acc.w += __shfl_xor_sync(0xffffffffu, acc.w, 16);
        if (half == 0) {
            float dn = dn_[k];
            float4 o;
            o.x = fmaxf(acc.x * dn + bb.x, 0.f);
            o.y = fmaxf(acc.y * dn + bb.y, 0.f);
            o.z = fmaxf(acc.z * dn + bb.z, 0.f);
            o.w = fmaxf(acc.w * dn + bb.w, 0.f);
            ((float4*)g_a)[n * 16 + l16] = o;
        }
    }
}

// ---------------- per-channel stats over g_a -> g_red1, + fused BN-param compute ----------------
__global__ void colstats_kernel(const float* __restrict__ gamma,
                                const float* __restrict__ beta) {
    __shared__ float sh[128];
    __shared__ int isLast;
    int t = threadIdx.x;
    if (t < 128) sh[t] = 0.f;
    __syncthreads();
    int c = t & 63;
    int tot = (gridDim.x * blockDim.x) >> 6;
    float s = 0.f, s2 = 0.f;
    for (int n = (blockIdx.x * blockDim.x + t) >> 6; n < NN; n += tot) {
        float v = g_a[n * 64 + c];
        s += v; s2 += v * v;
    }
    atomicAdd(&sh[c], s);
    atomicAdd(&sh[64 + c], s2);
    __syncthreads();
    if (t < 128) atomicAdd(&g_red1[t], sh[t]);
    __threadfence();
    if (t == 0) isLast = (atomicAdd(&g_ctr1, 1) == (int)gridDim.x - 1);
    __syncthreads();
    if (isLast && t < 64) {
        __threadfence();
        const float inv_n = 1.0f / (float)NN;
        float sum = atomicAdd(&g_red1[t], 0.f);
        float ssq = atomicAdd(&g_red1[64 + t], 0.f);
        float mu = sum * inv_n;
        float var = ssq * inv_n - mu * mu;
        float sc = gamma[t] * rsqrtf(var + EPS);
        g_pscale[t] = sc;
        g_pshift[t] = beta[t] - mu * sc;
        g_red1[t] = 0.f; g_red1[64 + t] = 0.f;
        if (t == 0) g_ctr1 = 0;
    }
}

// ---------------- pool: per-graph sums of g_a + global stats -> g_red2 ----------------
__global__ void pool_kernel() {
    int g = blockIdx.x;
    int n0 = g_gstart[g], n1 = g_gstart[g + 1];
    int t = threadIdx.x;
    int c = t & 63;
    float s = 0.f, s2 = 0.f;
    for (int n = n0 + (t >> 6); n < n1; n += 4) {
        float v = g_a[n * 64 + c];
        s += v; s2 += v * v;
    }
    __shared__ float sh[128];
    if (t < 128) sh[t] = 0.f;
    __syncthreads();
    atomicAdd(&sh[c], s);
    atomicAdd(&sh[64 + c], s2);
    __syncthreads();
    if (t < 64) {
        g_gsum[g * 64 + t] = sh[t];
        atomicAdd(&g_red2[t], sh[t]);
        atomicAdd(&g_red2[64 + t], sh[64 + t]);
    }
}

// ---------------- BN2 + mean + MLP head, one block per graph ----------------
__global__ void mlp_kernel(const float* __restrict__ gamma2, const float* __restrict__ beta2,
                           const float* __restrict__ fW1, const float* __restrict__ fb1,
                           const float* __restrict__ fW2, const float* __restrict__ fb2,
                           const float* __restrict__ fW3, const float* __restrict__ fb3,
                           const float* __restrict__ fW4, const float* __restrict__ fb4,
                           const float* __restrict__ oW, const float* __restrict__ ob,
                           float* __restrict__ out) {
    int g = blockIdx.x;
    int t = threadIdx.x;   // 128
    __shared__ float va[128], vb[128];
    const float inv_n = 1.0f / (float)NN;
    if (t < 64) {
        float mu = g_red2[t] * inv_n;
        float var = g_red2[64 + t] * inv_n - mu * mu;
        float sc = gamma2[t] * rsqrtf(var + EPS);
        float cnt = (float)(g_gstart[g + 1] - g_gstart[g]);
        cnt = fmaxf(cnt, 1.f);
        va[t] = (g_gsum[g * 64 + t] / cnt - mu) * sc + beta2[t];
    }
    __syncthreads();
    {   // 64 -> 128
        float acc = fb1[t];
        for (int k = 0; k < 64; k++) acc += va[k] * fW1[k * 128 + t];
        vb[t] = fmaxf(acc, 0.f);
    }
    __syncthreads();
    if (t < 64) {   // 128 -> 64
        float acc = fb2[t];
        for (int k = 0; k < 128; k++) acc += vb[k] * fW2[k * 64 + t];
        va[t] = fmaxf(acc, 0.f);
    }
    __syncthreads();
    if (t < 32) {   // 64 -> 32
        float acc = fb3[t];
        for (int k = 0; k < 64; k++) acc += va[k] * fW3[k * 32 + t];
        vb[t] = fmaxf(acc, 0.f);
    }
    __syncthreads();
    if (t < 16) {   // 32 -> 16
        float acc = fb4[t];
        for (int k = 0; k < 32; k++) acc += vb[k] * fW4[k * 16 + t];
        va[t] = fmaxf(acc, 0.f);
    }
    __syncthreads();
    if (t < 32) {   // 16 -> 1
        float p = (t < 16) ? va[t] * oW[t] : 0.f;
        #pragma unroll
        for (int off = 16; off; off >>= 1) p += __shfl_down_sync(0xffffffffu, p, off);
        if (t == 0) out[g] = p + ob[0];
    }
}

// ---------------- launch ----------------
extern "C" void kernel_launch(void* const* d_in, const int* in_sizes, int n_in,
                              void* d_out, int out_size) {
    const float* x      = (const float*)d_in[0];
    const int*   ei     = (const int*)d_in[1];
    const int*   batch  = (const int*)d_in[2];
    const float* W1     = (const float*)d_in[3];
    const float* b1     = (const float*)d_in[4];
    const float* W2     = (const float*)d_in[5];
    const float* b2     = (const float*)d_in[6];
    const float* gamma1 = (const float*)d_in[7];
    const float* beta1  = (const float*)d_in[8];
    const float* gamma2 = (const float*)d_in[9];
    const float* beta2  = (const float*)d_in[10];
    const float* fW1    = (const float*)d_in[11];
    const float* fb1    = (const float*)d_in[12];
    const float* fW2    = (const float*)d_in[13];
    const float* fb2    = (const float*)d_in[14];
    const float* fW3    = (const float*)d_in[15];
    const float* fb3    = (const float*)d_in[16];
    const float* fW4    = (const float*)d_in[17];
    const float* fb4    = (const float*)d_in[18];
    const float* oW     = (const float*)d_in[19];
    const float* ob     = (const float*)d_in[20];
    float* out = (float*)d_out;

    const int4* src4 = (const int4*)ei;
    const int4* dst4 = (const int4*)(ei + NE);

    const int nbE4 = (NE / 4 + 255) / 256;        // 1563
    const int nbG  = (NN + 127) / 128;            // 782
    const int nbA  = NWARPS / 8;                  // 3125 (4 nodes/warp)

    hist_kernel<<<nbE4, 256>>>(dst4, batch);                       // 0
    scan_kernel<<<NSB, 1024>>>();                                  // 1
    gemm_kernel<<<nbG, 256>>>(x, 128, W1, 0);                      // 2 (independent of fill)
    fill_kernel<<<nbE4, 256>>>(src4, dst4);                        // 3 <- profiled
    agg_kernel<<<nbA, 256>>>(b1);                                  // 4
    colstats_kernel<<<256, 256>>>(gamma1, beta1);                  // 5

    gemm_kernel<<<nbG, 256>>>(nullptr, 64, W2, 1);                 // 6
    agg_kernel<<<nbA, 256>>>(b2);                                  // 7

    pool_kernel<<<GG, 256>>>();                                    // 8
    mlp_kernel<<<GG, 128>>>(gamma2, beta2, fW1, fb1, fW2, fb2,
                            fW3, fb3, fW4, fb4, oW, ob, out);      // 9
}

// round 15
// speedup vs baseline: 1.1462x; 1.1462x over previous
#include <cuda_runtime.h>
#include <cuda_fp16.h>

#define NN 100000
#define NE 1600000
#define HH 64
#define GG 64
#define EPS 1e-5f
#define NSB 98            // scan blocks = ceil(NN/1024)

// ---------------- scratch (device globals; no allocations) ----------------
__device__ float g_hs[NN * HH];      // (X@W)*dinv fp32 (message source)
__device__ float g_a[NN * HH];       // activations a1 / a2
__device__ float g_dinv[NN];
__device__ int   g_hist[NN];         // zero-init; re-zeroed by scan each replay
__device__ int   g_rowptr[NN + 1];
__device__ int   g_cursor[NN];
__device__ int   g_perm[NE];
__device__ volatile int g_sstat[NSB];
__device__ volatile int g_sagg[NSB];
__device__ volatile int g_sinc[NSB];
__device__ float g_red1[128];        // BN1 stats (self-resetting via colstats)
__device__ float g_red2[128];        // BN2 stats (zeroed by scan)
__device__ int   g_ctr1;             // last-block counter (self-resetting)
__device__ float g_pscale[HH], g_pshift[HH];
__device__ float g_gsum[GG * HH];
__device__ int   g_gstart[GG + 1];

// ---------------- helpers ----------------
__device__ __forceinline__ float f2tf(float x) {
    unsigned y;
    asm("cvt.rna.tf32.f32 %0, %1;" : "=r"(y) : "f"(x));
    return __uint_as_float(y);
}
__device__ __forceinline__ void mma_tf32(float* d, const unsigned* a, const unsigned* b) {
    asm volatile(
        "mma.sync.aligned.m16n8k8.row.col.f32.tf32.tf32.f32 "
        "{%0,%1,%2,%3}, {%4,%5,%6,%7}, {%8,%9}, {%0,%1,%2,%3};\n"
        : "+f"(d[0]), "+f"(d[1]), "+f"(d[2]), "+f"(d[3])
        : "r"(a[0]), "r"(a[1]), "r"(a[2]), "r"(a[3]), "r"(b[0]), "r"(b[1]));
}

// ---------------- hist (+gstart search, +scan-flag reset) ----------------
__global__ void hist_kernel(const int4* __restrict__ dst4, const int* __restrict__ batch) {
    int e = blockIdx.x * 256 + threadIdx.x;
    if (blockIdx.x == 0) {
        if (threadIdx.x < NSB) g_sstat[threadIdx.x] = 0;
        if (threadIdx.x <= GG) {
            int g = threadIdx.x;
            int lo = 0, hi = NN;
            while (lo < hi) {
                int mid = (lo + hi) >> 1;
                if (batch[mid] < g) lo = mid + 1; else hi = mid;
            }
            g_gstart[g] = lo;
        }
    }
    if (e < NE / 4) {
        int4 d = dst4[e];
        atomicAdd(&g_hist[d.x], 1);
        atomicAdd(&g_hist[d.y], 1);
        atomicAdd(&g_hist[d.z], 1);
        atomicAdd(&g_hist[d.w], 1);
    }
}

// ---------------- single-pass scan (decoupled lookback) + dinv + zeroing ----------------
__global__ __launch_bounds__(1024) void scan_kernel() {
    __shared__ int sh[1024];
    __shared__ int s_excl;
    int t = threadIdx.x, b = blockIdx.x;
    int i = b * 1024 + t;
    int v = (i < NN) ? g_hist[i] : 0;
    if (i < NN) { g_dinv[i] = rsqrtf(1.0f + (float)v); g_hist[i] = 0; }
    if (b == 0 && t < 128) g_red2[t] = 0.f;
    sh[t] = v;
    __syncthreads();
    #pragma unroll
    for (int off = 1; off < 1024; off <<= 1) {
        int x = (t >= off) ? sh[t - off] : 0;
        __syncthreads();
        sh[t] += x;
        __syncthreads();
    }
    if (t == 0) {
        int total = sh[1023];
        if (b == 0) {
            g_sinc[0] = total; __threadfence(); g_sstat[0] = 2;
            s_excl = 0;
        } else {
            g_sagg[b] = total; __threadfence(); g_sstat[b] = 1;
            int ex = 0, j = b - 1;
            while (1) {
                int s;
                do { s = g_sstat[j]; } while (s == 0);
                if (s == 2) { ex += g_sinc[j]; break; }
                ex += g_sagg[j]; j--;
            }
            g_sinc[b] = ex + total; __threadfence(); g_sstat[b] = 2;
            s_excl = ex;
        }
    }
    __syncthreads();
    int excl = s_excl;
    if (i < NN) {
        int r = sh[t] - v + excl;
        g_rowptr[i] = r;
        g_cursor[i] = r;
    }
    if (i == 0) g_rowptr[NN] = NE;
}

__global__ void fill_kernel(const int4* __restrict__ src4, const int4* __restrict__ dst4) {
    int e = blockIdx.x * 256 + threadIdx.x;
    if (e < NE / 4) {
        int4 s = src4[e];
        int4 d = dst4[e];
        g_perm[atomicAdd(&g_cursor[d.x], 1)] = s.x;
        g_perm[atomicAdd(&g_cursor[d.y], 1)] = s.y;
        g_perm[atomicAdd(&g_cursor[d.z], 1)] = s.z;
        g_perm[atomicAdd(&g_cursor[d.w], 1)] = s.w;
    }
}

// ---------------- 3xTF32 GEMM: precomputed hi/lo split + register-prefetch pipeline ----------
// Block tile 128x64, 8 warps (32x32 warp tile), K chunk 32, mma m16n8k8.
// Next iteration's global loads issue BEFORE this iteration's MMA loop, hiding
// LDG latency behind tensor work.
__global__ __launch_bounds__(256) void gemm_kernel(const float* __restrict__ Xext, int K,
                                                   const float* __restrict__ W, int use_bn) {
    __shared__ float Ah[128][36];
    __shared__ float Al[128][36];
    __shared__ float Bh[32][68];
    __shared__ float Bl[32][68];
    const float* X = Xext ? Xext : g_a;
    int t = threadIdx.x;
    int w = t >> 5, lane = t & 31;
    int g = lane >> 2, tg = lane & 3;
    int mr = (w & 3) * 32;
    int nc = (w >> 2) * 32;
    int row0 = blockIdx.x * 128;

    // per-thread load coordinates
    int ar_ = t >> 3, ak4_ = (t & 7) * 4;        // A: 4 chunks of (row stride 32)
    int bk_ = t >> 4, bn4_ = (t & 15) * 4;       // B: 2 chunks of (k stride 16)

    float acc[2][4][4];
    #pragma unroll
    for (int a = 0; a < 2; a++)
        #pragma unroll
        for (int b = 0; b < 4; b++)
            #pragma unroll
            for (int c = 0; c < 4; c++) acc[a][b][c] = 0.f;

    float4 pa[4], pb[2];
    // prologue: load k0=0
    #pragma unroll
    for (int it = 0; it < 4; it++) {
        int r = ar_ + it * 32;
        int gr = row0 + r;
        float4 v = make_float4(0.f, 0.f, 0.f, 0.f);
        if (gr < NN) {
            v = *(const float4*)&X[gr * K + ak4_];
            if (use_bn) {
                v.x = v.x * g_pscale[ak4_ + 0] + g_pshift[ak4_ + 0];
                v.y = v.y * g_pscale[ak4_ + 1] + g_pshift[ak4_ + 1];
                v.z = v.z * g_pscale[ak4_ + 2] + g_pshift[ak4_ + 2];
                v.w = v.w * g_pscale[ak4_ + 3] + g_pshift[ak4_ + 3];
            }
        }
        pa[it] = v;
    }
    #pragma unroll
    for (int it = 0; it < 2; it++)
        pb[it] = *(const float4*)&W[(bk_ + it * 16) * 64 + bn4_];

    for (int k0 = 0; k0 < K; k0 += 32) {
        // store current regs -> smem with hi/lo split
        #pragma unroll
        for (int it = 0; it < 4; it++) {
            int r = ar_ + it * 32;
            float4 v = pa[it];
            float4 h = make_float4(f2tf(v.x), f2tf(v.y), f2tf(v.z), f2tf(v.w));
            float4 l = make_float4(f2tf(v.x - h.x), f2tf(v.y - h.y),
                                   f2tf(v.z - h.z), f2tf(v.w - h.w));
            *(float4*)&Ah[r][ak4_] = h;
            *(float4*)&Al[r][ak4_] = l;
        }
        #pragma unroll
        for (int it = 0; it < 2; it++) {
            float4 v = pb[it];
            float4 h = make_float4(f2tf(v.x), f2tf(v.y), f2tf(v.z), f2tf(v.w));
            float4 l = make_float4(f2tf(v.x - h.x), f2tf(v.y - h.y),
                                   f2tf(v.z - h.z), f2tf(v.w - h.w));
            *(float4*)&Bh[bk_ + it * 16][bn4_] = h;
            *(float4*)&Bl[bk_ + it * 16][bn4_] = l;
        }
        __syncthreads();

        // prefetch next iteration's gmem data (overlaps with MMA below)
        int kn = k0 + 32;
        if (kn < K) {
            #pragma unroll
            for (int it = 0; it < 4; it++) {
                int r = ar_ + it * 32;
                int gr = row0 + r;
                float4 v = make_float4(0.f, 0.f, 0.f, 0.f);
                if (gr < NN) {
                    int kb = kn + ak4_;
                    v = *(const float4*)&X[gr * K + kb];
                    if (use_bn) {
                        v.x = v.x * g_pscale[kb + 0] + g_pshift[kb + 0];
                        v.y = v.y * g_pscale[kb + 1] + g_pshift[kb + 1];
                        v.z = v.z * g_pscale[kb + 2] + g_pshift[kb + 2];
                        v.w = v.w * g_pscale[kb + 3] + g_pshift[kb + 3];
                    }
                }
                pa[it] = v;
            }
            #pragma unroll
            for (int it = 0; it < 2; it++)
                pb[it] = *(const float4*)&W[(kn + bk_ + it * 16) * 64 + bn4_];
        }

        #pragma unroll
        for (int ks = 0; ks < 32; ks += 8) {
            unsigned ah[2][4], al[2][4], bh[4][2], bl[4][2];
            #pragma unroll
            for (int mt = 0; mt < 2; mt++) {
                int brow = mr + mt * 16;
                ah[mt][0] = __float_as_uint(Ah[brow + g][ks + tg]);
                ah[mt][1] = __float_as_uint(Ah[brow + g + 8][ks + tg]);
                ah[mt][2] = __float_as_uint(Ah[brow + g][ks + tg + 4]);
                ah[mt][3] = __float_as_uint(Ah[brow + g + 8][ks + tg + 4]);
                al[mt][0] = __float_as_uint(Al[brow + g][ks + tg]);
                al[mt][1] = __float_as_uint(Al[brow + g + 8][ks + tg]);
                al[mt][2] = __float_as_uint(Al[brow + g][ks + tg + 4]);
                al[mt][3] = __float_as_uint(Al[brow + g + 8][ks + tg + 4]);
            }
            #pragma unroll
            for (int nt = 0; nt < 4; nt++) {
                int col = nc + nt * 8 + g;
                bh[nt][0] = __float_as_uint(Bh[ks + tg][col]);
                bh[nt][1] = __float_as_uint(Bh[ks + tg + 4][col]);
                bl[nt][0] = __float_as_uint(Bl[ks + tg][col]);
                bl[nt][1] = __float_as_uint(Bl[ks + tg + 4][col]);
            }
            #pragma unroll
            for (int mt = 0; mt < 2; mt++)
                #pragma unroll
                for (int nt = 0; nt < 4; nt++) {
                    mma_tf32(acc[mt][nt], ah[mt], bl[nt]);
                    mma_tf32(acc[mt][nt], al[mt], bh[nt]);
                    mma_tf32(acc[mt][nt], ah[mt], bh[nt]);
                }
        }
        __syncthreads();
    }

    #pragma unroll
    for (int mt = 0; mt < 2; mt++) {
        int r0g = row0 + mr + mt * 16 + g;
        int r1g = r0g + 8;
        float dn0 = (r0g < NN) ? g_dinv[r0g] : 0.f;
        float dn1 = (r1g < NN) ? g_dinv[r1g] : 0.f;
        #pragma unroll
        for (int nt = 0; nt < 4; nt++) {
            int col = nc + nt * 8 + tg * 2;
            if (r0g < NN)
                *(float2*)&g_hs[r0g * 64 + col] =
                    make_float2(acc[mt][nt][0] * dn0, acc[mt][nt][1] * dn0);
            if (r1g < NN)
                *(float2*)&g_hs[r1g * 64 + col] =
                    make_float2(acc[mt][nt][2] * dn1, acc[mt][nt][3] * dn1);
        }
    }
}

// ---------------- aggregation: half-warp per node, float4 gathers (R6 version) -----------
__global__ void agg_kernel(const float* __restrict__ bias) {
    int t = threadIdx.x;
    int hw = t >> 4;                      // half-warp id in block (0..15)
    int l16 = t & 15;
    int n = blockIdx.x * 16 + hw;
    if (n >= NN) return;
    const float4* h4 = (const float4*)g_hs;
    float4 acc = h4[n * 16 + l16];        // self term (already *dinv[src])
    int e = g_rowptr[n], end = g_rowptr[n + 1];
    while (__any_sync(0xffffffffu, e < end)) {
        int cnt = end - e; if (cnt > 16) cnt = 16; if (cnt < 0) cnt = 0;
        int s = (l16 < cnt) ? g_perm[e + l16] : 0;
        int mcnt = max(cnt, __shfl_xor_sync(0xffffffffu, cnt, 16));
        for (int i = 0; i < mcnt; i += 4) {
            #pragma unroll
            for (int j = 0; j < 4; j++) {
                int si = __shfl_sync(0xffffffffu, s, i + j, 16);
                if (i + j < cnt) {
                    float4 v = h4[si * 16 + l16];
                    acc.x += v.x; acc.y += v.y; acc.z += v.z; acc.w += v.w;
                }
            }
        }
        e += cnt;
    }
    float dn = g_dinv[n];
    float4 bb = ((const float4*)bias)[l16];
    float4 o;
    o.x = fmaxf(acc.x * dn + bb.x, 0.f);
    o.y = fmaxf(acc.y * dn + bb.y, 0.f);
    o.z = fmaxf(acc.z * dn + bb.z, 0.f);
    o.w = fmaxf(acc.w * dn + bb.w, 0.f);
    ((float4*)g_a)[n * 16 + l16] = o;
}

// ---------------- per-channel stats over g_a -> g_red1, + fused BN-param compute ----------------
__global__ void colstats_kernel(const float* __restrict__ gamma,
                                const float* __restrict__ beta) {
    __shared__ float sh[128];
    __shared__ int isLast;
    int t = threadIdx.x;
    if (t < 128) sh[t] = 0.f;
    __syncthreads();
    int c = t & 63;
    int tot = (gridDim.x * blockDim.x) >> 6;
    float s = 0.f, s2 = 0.f;
    for (int n = (blockIdx.x * blockDim.x + t) >> 6; n < NN; n += tot) {
        float v = g_a[n * 64 + c];
        s += v; s2 += v * v;
    }
    atomicAdd(&sh[c], s);
    atomicAdd(&sh[64 + c], s2);
    __syncthreads();
    if (t < 128) atomicAdd(&g_red1[t], sh[t]);
    __threadfence();
    if (t == 0) isLast = (atomicAdd(&g_ctr1, 1) == (int)gridDim.x - 1);
    __syncthreads();
    if (isLast && t < 64) {
        __threadfence();
        const float inv_n = 1.0f / (float)NN;
        float sum = atomicAdd(&g_red1[t], 0.f);
        float ssq = atomicAdd(&g_red1[64 + t], 0.f);
        float mu = sum * inv_n;
        float var = ssq * inv_n - mu * mu;
        float sc = gamma[t] * rsqrtf(var + EPS);
        g_pscale[t] = sc;
        g_pshift[t] = beta[t] - mu * sc;
        g_red1[t] = 0.f; g_red1[64 + t] = 0.f;     // reset for next replay
        if (t == 0) g_ctr1 = 0;
    }
}

// ---------------- pool: per-graph sums of g_a + global stats -> g_red2 ----------------
__global__ void pool_kernel() {
    int g = blockIdx.x;
    int n0 = g_gstart[g], n1 = g_gstart[g + 1];
    int t = threadIdx.x;
    int c = t & 63;
    float s = 0.f, s2 = 0.f;
    for (int n = n0 + (t >> 6); n < n1; n += 4) {
        float v = g_a[n * 64 + c];
        s += v; s2 += v * v;
    }
    __shared__ float sh[128];
    if (t < 128) sh[t] = 0.f;
    __syncthreads();
    atomicAdd(&sh[c], s);
    atomicAdd(&sh[64 + c], s2);
    __syncthreads();
    if (t < 64) {
        g_gsum[g * 64 + t] = sh[t];
        atomicAdd(&g_red2[t], sh[t]);
        atomicAdd(&g_red2[64 + t], sh[64 + t]);
    }
}

// ---------------- BN2 + mean + MLP head, one block per graph ----------------
__global__ void mlp_kernel(const float* __restrict__ gamma2, const float* __restrict__ beta2,
                           const float* __restrict__ fW1, const float* __restrict__ fb1,
                           const float* __restrict__ fW2, const float* __restrict__ fb2,
                           const float* __restrict__ fW3, const float* __restrict__ fb3,
                           const float* __restrict__ fW4, const float* __restrict__ fb4,
                           const float* __restrict__ oW, const float* __restrict__ ob,
                           float* __restrict__ out) {
    int g = blockIdx.x;
    int t = threadIdx.x;   // 128
    __shared__ float va[128], vb[128];
    const float inv_n = 1.0f / (float)NN;
    if (t < 64) {
        float mu = g_red2[t] * inv_n;
        float var = g_red2[64 + t] * inv_n - mu * mu;
        float sc = gamma2[t] * rsqrtf(var + EPS);
        float cnt = (float)(g_gstart[g + 1] - g_gstart[g]);
        cnt = fmaxf(cnt, 1.f);
        va[t] = (g_gsum[g * 64 + t] / cnt - mu) * sc + beta2[t];
    }
    __syncthreads();
    {   // 64 -> 128
        float acc = fb1[t];
        for (int k = 0; k < 64; k++) acc += va[k] * fW1[k * 128 + t];
        vb[t] = fmaxf(acc, 0.f);
    }
    __syncthreads();
    if (t < 64) {   // 128 -> 64
        float acc = fb2[t];
        for (int k = 0; k < 128; k++) acc += vb[k] * fW2[k * 64 + t];
        va[t] = fmaxf(acc, 0.f);
    }
    __syncthreads();
    if (t < 32) {   // 64 -> 32
        float acc = fb3[t];
        for (int k = 0; k < 64; k++) acc += va[k] * fW3[k * 32 + t];
        vb[t] = fmaxf(acc, 0.f);
    }
    __syncthreads();
    if (t < 16) {   // 32 -> 16
        float acc = fb4[t];
        for (int k = 0; k < 32; k++) acc += vb[k] * fW4[k * 16 + t];
        va[t] = fmaxf(acc, 0.f);
    }
    __syncthreads();
    if (t < 32) {   // 16 -> 1
        float p = (t < 16) ? va[t] * oW[t] : 0.f;
        #pragma unroll
        for (int off = 16; off; off >>= 1) p += __shfl_down_sync(0xffffffffu, p, off);
        if (t == 0) out[g] = p + ob[0];
    }
}

// ---------------- launch ----------------
extern "C" void kernel_launch(void* const* d_in, const int* in_sizes, int n_in,
                              void* d_out, int out_size) {
    const float* x      = (const float*)d_in[0];
    const int*   ei     = (const int*)d_in[1];
    const int*   batch  = (const int*)d_in[2];
    const float* W1     = (const float*)d_in[3];
    const float* b1     = (const float*)d_in[4];
    const float* W2     = (const float*)d_in[5];
    const float* b2     = (const float*)d_in[6];
    const float* gamma1 = (const float*)d_in[7];
    const float* beta1  = (const float*)d_in[8];
    const float* gamma2 = (const float*)d_in[9];
    const float* beta2  = (const float*)d_in[10];
    const float* fW1    = (const float*)d_in[11];
    const float* fb1    = (const float*)d_in[12];
    const float* fW2    = (const float*)d_in[13];
    const float* fb2    = (const float*)d_in[14];
    const float* fW3    = (const float*)d_in[15];
    const float* fb3    = (const float*)d_in[16];
    const float* fW4    = (const float*)d_in[17];
    const float* fb4    = (const float*)d_in[18];
    const float* oW     = (const float*)d_in[19];
    const float* ob     = (const float*)d_in[20];
    float* out = (float*)d_out;

    const int4* src4 = (const int4*)ei;
    const int4* dst4 = (const int4*)(ei + NE);

    const int nbE4 = (NE / 4 + 255) / 256;        // 1563
    const int nbG  = (NN + 127) / 128;            // 782
    const int nbA  = (NN + 15) / 16;              // 6250 (16 nodes/block)

    hist_kernel<<<nbE4, 256>>>(dst4, batch);                       // 0
    scan_kernel<<<NSB, 1024>>>();                                  // 1
    fill_kernel<<<nbE4, 256>>>(src4, dst4);                        // 2

    gemm_kernel<<<nbG, 256>>>(x, 128, W1, 0);                      // 3 <- profiled
    agg_kernel<<<nbA, 256>>>(b1);                                  // 4
    colstats_kernel<<<256, 256>>>(gamma1, beta1);                  // 5

    gemm_kernel<<<nbG, 256>>>(nullptr, 64, W2, 1);                 // 6
    agg_kernel<<<nbA, 256>>>(b2);                                  // 7

    pool_kernel<<<GG, 256>>>();                                    // 8
    mlp_kernel<<<GG, 128>>>(gamma2, beta2, fW1, fb1, fW2, fb2,
                            fW3, fb3, fW4, fb4, oW, ob, out);      // 9
}

// round 16
// speedup vs baseline: 1.1609x; 1.0128x over previous
#include <cuda_runtime.h>
#include <cuda_fp16.h>

#define NN 100000
#define NE 1600000
#define HH 64
#define GG 64
#define EPS 1e-5f
#define NSB 98            // scan blocks = ceil(NN/1024)

// ---------------- scratch (device globals; no allocations) ----------------
__device__ float g_hs[NN * HH];      // (X@W)*dinv fp32 (message source)
__device__ float g_a[NN * HH];       // activations a1 / a2
__device__ float g_dinv[NN];
__device__ int   g_hist[NN];         // zero-init; re-zeroed by scan each replay
__device__ int   g_rowptr[NN + 1];
__device__ int   g_cursor[NN];
__device__ int   g_perm[NE];
__device__ volatile int g_sstat[NSB];
__device__ volatile int g_sagg[NSB];
__device__ volatile int g_sinc[NSB];
__device__ float g_red1[128];        // BN1 stats (self-resetting via colstats)
__device__ float g_red2[128];        // BN2 stats (zeroed by scan)
__device__ int   g_ctr1;             // last-block counter (self-resetting)
__device__ float g_pscale[HH], g_pshift[HH];
__device__ float g_gsum[GG * HH];
__device__ int   g_gstart[GG + 1];

// ---------------- helpers ----------------
__device__ __forceinline__ float f2tf(float x) {
    unsigned y;
    asm("cvt.rna.tf32.f32 %0, %1;" : "=r"(y) : "f"(x));
    return __uint_as_float(y);
}
__device__ __forceinline__ void mma_tf32(float* d, const unsigned* a, const unsigned* b) {
    asm volatile(
        "mma.sync.aligned.m16n8k8.row.col.f32.tf32.tf32.f32 "
        "{%0,%1,%2,%3}, {%4,%5,%6,%7}, {%8,%9}, {%0,%1,%2,%3};\n"
        : "+f"(d[0]), "+f"(d[1]), "+f"(d[2]), "+f"(d[3])
        : "r"(a[0]), "r"(a[1]), "r"(a[2]), "r"(a[3]), "r"(b[0]), "r"(b[1]));
}

// ---------------- hist (+gstart search, +scan-flag reset) ----------------
__global__ void hist_kernel(const int4* __restrict__ dst4, const int* __restrict__ batch) {
    int e = blockIdx.x * 256 + threadIdx.x;
    if (blockIdx.x == 0) {
        if (threadIdx.x < NSB) g_sstat[threadIdx.x] = 0;
        if (threadIdx.x <= GG) {
            int g = threadIdx.x;
            int lo = 0, hi = NN;
            while (lo < hi) {
                int mid = (lo + hi) >> 1;
                if (batch[mid] < g) lo = mid + 1; else hi = mid;
            }
            g_gstart[g] = lo;
        }
    }
    if (e < NE / 4) {
        int4 d = dst4[e];
        atomicAdd(&g_hist[d.x], 1);
        atomicAdd(&g_hist[d.y], 1);
        atomicAdd(&g_hist[d.z], 1);
        atomicAdd(&g_hist[d.w], 1);
    }
}

// ---------------- single-pass scan (decoupled lookback) + dinv + zeroing ----------------
__global__ __launch_bounds__(1024) void scan_kernel() {
    __shared__ int sh[1024];
    __shared__ int s_excl;
    int t = threadIdx.x, b = blockIdx.x;
    int i = b * 1024 + t;
    int v = (i < NN) ? g_hist[i] : 0;
    if (i < NN) { g_dinv[i] = rsqrtf(1.0f + (float)v); g_hist[i] = 0; }
    if (b == 0 && t < 128) g_red2[t] = 0.f;
    sh[t] = v;
    __syncthreads();
    #pragma unroll
    for (int off = 1; off < 1024; off <<= 1) {
        int x = (t >= off) ? sh[t - off] : 0;
        __syncthreads();
        sh[t] += x;
        __syncthreads();
    }
    if (t == 0) {
        int total = sh[1023];
        if (b == 0) {
            g_sinc[0] = total; __threadfence(); g_sstat[0] = 2;
            s_excl = 0;
        } else {
            g_sagg[b] = total; __threadfence(); g_sstat[b] = 1;
            int ex = 0, j = b - 1;
            while (1) {
                int s;
                do { s = g_sstat[j]; } while (s == 0);
                if (s == 2) { ex += g_sinc[j]; break; }
                ex += g_sagg[j]; j--;
            }
            g_sinc[b] = ex + total; __threadfence(); g_sstat[b] = 2;
            s_excl = ex;
        }
    }
    __syncthreads();
    int excl = s_excl;
    if (i < NN) {
        int r = sh[t] - v + excl;
        g_rowptr[i] = r;
        g_cursor[i] = r;
    }
    if (i == 0) g_rowptr[NN] = NE;
}

__global__ void fill_kernel(const int4* __restrict__ src4, const int4* __restrict__ dst4) {
    int e = blockIdx.x * 256 + threadIdx.x;
    if (e < NE / 4) {
        int4 s = src4[e];
        int4 d = dst4[e];
        g_perm[atomicAdd(&g_cursor[d.x], 1)] = s.x;
        g_perm[atomicAdd(&g_cursor[d.y], 1)] = s.y;
        g_perm[atomicAdd(&g_cursor[d.z], 1)] = s.z;
        g_perm[atomicAdd(&g_cursor[d.w], 1)] = s.w;
    }
}

// ---------------- 3xTF32 GEMM: precomputed hi/lo split + register-prefetch pipeline ----------
// Block tile 128x64, 8 warps (32x32 warp tile), K chunk 32, mma m16n8k8.
__global__ __launch_bounds__(256) void gemm_kernel(const float* __restrict__ Xext, int K,
                                                   const float* __restrict__ W, int use_bn) {
    __shared__ float Ah[128][36];
    __shared__ float Al[128][36];
    __shared__ float Bh[32][68];
    __shared__ float Bl[32][68];
    const float* X = Xext ? Xext : g_a;
    int t = threadIdx.x;
    int w = t >> 5, lane = t & 31;
    int g = lane >> 2, tg = lane & 3;
    int mr = (w & 3) * 32;
    int nc = (w >> 2) * 32;
    int row0 = blockIdx.x * 128;

    int ar_ = t >> 3, ak4_ = (t & 7) * 4;
    int bk_ = t >> 4, bn4_ = (t & 15) * 4;

    float acc[2][4][4];
    #pragma unroll
    for (int a = 0; a < 2; a++)
        #pragma unroll
        for (int b = 0; b < 4; b++)
            #pragma unroll
            for (int c = 0; c < 4; c++) acc[a][b][c] = 0.f;

    float4 pa[4], pb[2];
    #pragma unroll
    for (int it = 0; it < 4; it++) {
        int r = ar_ + it * 32;
        int gr = row0 + r;
        float4 v = make_float4(0.f, 0.f, 0.f, 0.f);
        if (gr < NN) {
            v = *(const float4*)&X[gr * K + ak4_];
            if (use_bn) {
                v.x = v.x * g_pscale[ak4_ + 0] + g_pshift[ak4_ + 0];
                v.y = v.y * g_pscale[ak4_ + 1] + g_pshift[ak4_ + 1];
                v.z = v.z * g_pscale[ak4_ + 2] + g_pshift[ak4_ + 2];
                v.w = v.w * g_pscale[ak4_ + 3] + g_pshift[ak4_ + 3];
            }
        }
        pa[it] = v;
    }
    #pragma unroll
    for (int it = 0; it < 2; it++)
        pb[it] = *(const float4*)&W[(bk_ + it * 16) * 64 + bn4_];

    for (int k0 = 0; k0 < K; k0 += 32) {
        #pragma unroll
        for (int it = 0; it < 4; it++) {
            int r = ar_ + it * 32;
            float4 v = pa[it];
            float4 h = make_float4(f2tf(v.x), f2tf(v.y), f2tf(v.z), f2tf(v.w));
            float4 l = make_float4(f2tf(v.x - h.x), f2tf(v.y - h.y),
                                   f2tf(v.z - h.z), f2tf(v.w - h.w));
            *(float4*)&Ah[r][ak4_] = h;
            *(float4*)&Al[r][ak4_] = l;
        }
        #pragma unroll
        for (int it = 0; it < 2; it++) {
            float4 v = pb[it];
            float4 h = make_float4(f2tf(v.x), f2tf(v.y), f2tf(v.z), f2tf(v.w));
            float4 l = make_float4(f2tf(v.x - h.x), f2tf(v.y - h.y),
                                   f2tf(v.z - h.z), f2tf(v.w - h.w));
            *(float4*)&Bh[bk_ + it * 16][bn4_] = h;
            *(float4*)&Bl[bk_ + it * 16][bn4_] = l;
        }
        __syncthreads();

        int kn = k0 + 32;
        if (kn < K) {
            #pragma unroll
            for (int it = 0; it < 4; it++) {
                int r = ar_ + it * 32;
                int gr = row0 + r;
                float4 v = make_float4(0.f, 0.f, 0.f, 0.f);
                if (gr < NN) {
                    int kb = kn + ak4_;
                    v = *(const float4*)&X[gr * K + kb];
                    if (use_bn) {
                        v.x = v.x * g_pscale[kb + 0] + g_pshift[kb + 0];
                        v.y = v.y * g_pscale[kb + 1] + g_pshift[kb + 1];
                        v.z = v.z * g_pscale[kb + 2] + g_pshift[kb + 2];
                        v.w = v.w * g_pscale[kb + 3] + g_pshift[kb + 3];
                    }
                }
                pa[it] = v;
            }
            #pragma unroll
            for (int it = 0; it < 2; it++)
                pb[it] = *(const float4*)&W[(kn + bk_ + it * 16) * 64 + bn4_];
        }

        #pragma unroll
        for (int ks = 0; ks < 32; ks += 8) {
            unsigned ah[2][4], al[2][4], bh[4][2], bl[4][2];
            #pragma unroll
            for (int mt = 0; mt < 2; mt++) {
                int brow = mr + mt * 16;
                ah[mt][0] = __float_as_uint(Ah[brow + g][ks + tg]);
                ah[mt][1] = __float_as_uint(Ah[brow + g + 8][ks + tg]);
                ah[mt][2] = __float_as_uint(Ah[brow + g][ks + tg + 4]);
                ah[mt][3] = __float_as_uint(Ah[brow + g + 8][ks + tg + 4]);
                al[mt][0] = __float_as_uint(Al[brow + g][ks + tg]);
                al[mt][1] = __float_as_uint(Al[brow + g + 8][ks + tg]);
                al[mt][2] = __float_as_uint(Al[brow + g][ks + tg + 4]);
                al[mt][3] = __float_as_uint(Al[brow + g + 8][ks + tg + 4]);
            }
            #pragma unroll
            for (int nt = 0; nt < 4; nt++) {
                int col = nc + nt * 8 + g;
                bh[nt][0] = __float_as_uint(Bh[ks + tg][col]);
                bh[nt][1] = __float_as_uint(Bh[ks + tg + 4][col]);
                bl[nt][0] = __float_as_uint(Bl[ks + tg][col]);
                bl[nt][1] = __float_as_uint(Bl[ks + tg + 4][col]);
            }
            #pragma unroll
            for (int mt = 0; mt < 2; mt++)
                #pragma unroll
                for (int nt = 0; nt < 4; nt++) {
                    mma_tf32(acc[mt][nt], ah[mt], bl[nt]);
                    mma_tf32(acc[mt][nt], al[mt], bh[nt]);
                    mma_tf32(acc[mt][nt], ah[mt], bh[nt]);
                }
        }
        __syncthreads();
    }

    #pragma unroll
    for (int mt = 0; mt < 2; mt++) {
        int r0g = row0 + mr + mt * 16 + g;
        int r1g = r0g + 8;
        float dn0 = (r0g < NN) ? g_dinv[r0g] : 0.f;
        float dn1 = (r1g < NN) ? g_dinv[r1g] : 0.f;
        #pragma unroll
        for (int nt = 0; nt < 4; nt++) {
            int col = nc + nt * 8 + tg * 2;
            if (r0g < NN)
                *(float2*)&g_hs[r0g * 64 + col] =
                    make_float2(acc[mt][nt][0] * dn0, acc[mt][nt][1] * dn0);
            if (r1g < NN)
                *(float2*)&g_hs[r1g * 64 + col] =
                    make_float2(acc[mt][nt][2] * dn1, acc[mt][nt][3] * dn1);
        }
    }
}

// ---------------- aggregation: half-warp per node, float4 gathers (R6 version) -----------
__global__ void agg_kernel(const float* __restrict__ bias) {
    int t = threadIdx.x;
    int hw = t >> 4;                      // half-warp id in block (0..15)
    int l16 = t & 15;
    int n = blockIdx.x * 16 + hw;
    if (n >= NN) return;
    const float4* h4 = (const float4*)g_hs;
    float4 acc = h4[n * 16 + l16];        // self term (already *dinv[src])
    int e = g_rowptr[n], end = g_rowptr[n + 1];
    while (__any_sync(0xffffffffu, e < end)) {
        int cnt = end - e; if (cnt > 16) cnt = 16; if (cnt < 0) cnt = 0;
        int s = (l16 < cnt) ? g_perm[e + l16] : 0;
        int mcnt = max(cnt, __shfl_xor_sync(0xffffffffu, cnt, 16));
        for (int i = 0; i < mcnt; i += 4) {
            #pragma unroll
            for (int j = 0; j < 4; j++) {
                int si = __shfl_sync(0xffffffffu, s, i + j, 16);
                if (i + j < cnt) {
                    float4 v = h4[si * 16 + l16];
                    acc.x += v.x; acc.y += v.y; acc.z += v.z; acc.w += v.w;
                }
            }
        }
        e += cnt;
    }
    float dn = g_dinv[n];
    float4 bb = ((const float4*)bias)[l16];
    float4 o;
    o.x = fmaxf(acc.x * dn + bb.x, 0.f);
    o.y = fmaxf(acc.y * dn + bb.y, 0.f);
    o.z = fmaxf(acc.z * dn + bb.z, 0.f);
    o.w = fmaxf(acc.w * dn + bb.w, 0.f);
    ((float4*)g_a)[n * 16 + l16] = o;
}

// ---------------- per-channel stats over g_a -> g_red1, + fused BN-param compute ----------------
__global__ void colstats_kernel(const float* __restrict__ gamma,
                                const float* __restrict__ beta) {
    __shared__ float sh[128];
    __shared__ int isLast;
    int t = threadIdx.x;
    if (t < 128) sh[t] = 0.f;
    __syncthreads();
    int c = t & 63;
    int tot = (gridDim.x * blockDim.x) >> 6;
    float s = 0.f, s2 = 0.f;
    for (int n = (blockIdx.x * blockDim.x + t) >> 6; n < NN; n += tot) {
        float v = g_a[n * 64 + c];
        s += v; s2 += v * v;
    }
    atomicAdd(&sh[c], s);
    atomicAdd(&sh[64 + c], s2);
    __syncthreads();
    if (t < 128) atomicAdd(&g_red1[t], sh[t]);
    __threadfence();
    if (t == 0) isLast = (atomicAdd(&g_ctr1, 1) == (int)gridDim.x - 1);
    __syncthreads();
    if (isLast && t < 64) {
        __threadfence();
        const float inv_n = 1.0f / (float)NN;
        float sum = atomicAdd(&g_red1[t], 0.f);
        float ssq = atomicAdd(&g_red1[64 + t], 0.f);
        float mu = sum * inv_n;
        float var = ssq * inv_n - mu * mu;
        float sc = gamma[t] * rsqrtf(var + EPS);
        g_pscale[t] = sc;
        g_pshift[t] = beta[t] - mu * sc;
        g_red1[t] = 0.f; g_red1[64 + t] = 0.f;     // reset for next replay
        if (t == 0) g_ctr1 = 0;
    }
}

// ---------------- pool: per-graph sums of g_a + global stats -> g_red2 ----------------
__global__ void pool_kernel() {
    int g = blockIdx.x;
    int n0 = g_gstart[g], n1 = g_gstart[g + 1];
    int t = threadIdx.x;
    int c = t & 63;
    float s = 0.f, s2 = 0.f;
    for (int n = n0 + (t >> 6); n < n1; n += 4) {
        float v = g_a[n * 64 + c];
        s += v; s2 += v * v;
    }
    __shared__ float sh[128];
    if (t < 128) sh[t] = 0.f;
    __syncthreads();
    atomicAdd(&sh[c], s);
    atomicAdd(&sh[64 + c], s2);
    __syncthreads();
    if (t < 64) {
        g_gsum[g * 64 + t] = sh[t];
        atomicAdd(&g_red2[t], sh[t]);
        atomicAdd(&g_red2[64 + t], sh[64 + t]);
    }
}

// ---------------- BN2 + mean + MLP head, one block per graph ----------------
__global__ void mlp_kernel(const float* __restrict__ gamma2, const float* __restrict__ beta2,
                           const float* __restrict__ fW1, const float* __restrict__ fb1,
                           const float* __restrict__ fW2, const float* __restrict__ fb2,
                           const float* __restrict__ fW3, const float* __restrict__ fb3,
                           const float* __restrict__ fW4, const float* __restrict__ fb4,
                           const float* __restrict__ oW, const float* __restrict__ ob,
                           float* __restrict__ out) {
    int g = blockIdx.x;
    int t = threadIdx.x;   // 128
    __shared__ float va[128], vb[128];
    const float inv_n = 1.0f / (float)NN;
    if (t < 64) {
        float mu = g_red2[t] * inv_n;
        float var = g_red2[64 + t] * inv_n - mu * mu;
        float sc = gamma2[t] * rsqrtf(var + EPS);
        float cnt = (float)(g_gstart[g + 1] - g_gstart[g]);
        cnt = fmaxf(cnt, 1.f);
        va[t] = (g_gsum[g * 64 + t] / cnt - mu) * sc + beta2[t];
    }
    __syncthreads();
    {   // 64 -> 128
        float acc = fb1[t];
        for (int k = 0; k < 64; k++) acc += va[k] * fW1[k * 128 + t];
        vb[t] = fmaxf(acc, 0.f);
    }
    __syncthreads();
    if (t < 64) {   // 128 -> 64
        float acc = fb2[t];
        for (int k = 0; k < 128; k++) acc += vb[k] * fW2[k * 64 + t];
        va[t] = fmaxf(acc, 0.f);
    }
    __syncthreads();
    if (t < 32) {   // 64 -> 32
        float acc = fb3[t];
        for (int k = 0; k < 64; k++) acc += va[k] * fW3[k * 32 + t];
        vb[t] = fmaxf(acc, 0.f);
    }
    __syncthreads();
    if (t < 16) {   // 32 -> 16
        float acc = fb4[t];
        for (int k = 0; k < 32; k++) acc += vb[k] * fW4[k * 16 + t];
        va[t] = fmaxf(acc, 0.f);
    }
    __syncthreads();
    if (t < 32) {   // 16 -> 1
        float p = (t < 16) ? va[t] * oW[t] : 0.f;
        #pragma unroll
        for (int off = 16; off; off >>= 1) p += __shfl_down_sync(0xffffffffu, p, off);
        if (t == 0) out[g] = p + ob[0];
    }
}

// ---------------- launch: fork-join so fill (latency-bound) overlaps gemm1 (tensor-bound) ----
extern "C" void kernel_launch(void* const* d_in, const int* in_sizes, int n_in,
                              void* d_out, int out_size) {
    const float* x      = (const float*)d_in[0];
    const int*   ei     = (const int*)d_in[1];
    const int*   batch  = (const int*)d_in[2];
    const float* W1     = (const float*)d_in[3];
    const float* b1     = (const float*)d_in[4];
    const float* W2     = (const float*)d_in[5];
    const float* b2     = (const float*)d_in[6];
    const float* gamma1 = (const float*)d_in[7];
    const float* beta1  = (const float*)d_in[8];
    const float* gamma2 = (const float*)d_in[9];
    const float* beta2  = (const float*)d_in[10];
    const float* fW1    = (const float*)d_in[11];
    const float* fb1    = (const float*)d_in[12];
    const float* fW2    = (const float*)d_in[13];
    const float* fb2    = (const float*)d_in[14];
    const float* fW3    = (const float*)d_in[15];
    const float* fb3    = (const float*)d_in[16];
    const float* fW4    = (const float*)d_in[17];
    const float* fb4    = (const float*)d_in[18];
    const float* oW     = (const float*)d_in[19];
    const float* ob     = (const float*)d_in[20];
    float* out = (float*)d_out;

    const int4* src4 = (const int4*)ei;
    const int4* dst4 = (const int4*)(ei + NE);

    const int nbE4 = (NE / 4 + 255) / 256;        // 1563
    const int nbG  = (NN + 127) / 128;            // 782
    const int nbA  = (NN + 15) / 16;              // 6250 (16 nodes/block)

    // one-time side-stream + events (host objects; created on the first,
    // non-capturing correctness call and reused by the captured graph)
    static cudaStream_t s2 = 0;
    static cudaEvent_t evFork = 0, evJoin = 0;
    static int sinit = 0;
    if (!sinit) {
        if (cudaStreamCreateWithFlags(&s2, cudaStreamNonBlocking) != cudaSuccess) s2 = 0;
        if (cudaEventCreateWithFlags(&evFork, cudaEventDisableTiming) != cudaSuccess) evFork = 0;
        if (cudaEventCreateWithFlags(&evJoin, cudaEventDisableTiming) != cudaSuccess) evJoin = 0;
        sinit = 1;
    }
    const bool fork = (s2 && evFork && evJoin);

    hist_kernel<<<nbE4, 256>>>(dst4, batch);                       // 0
    scan_kernel<<<NSB, 1024>>>();                                  // 1

    if (fork) {
        cudaEventRecord(evFork, 0);
        cudaStreamWaitEvent(s2, evFork, 0);
        fill_kernel<<<nbE4, 256, 0, s2>>>(src4, dst4);             // side stream
        gemm_kernel<<<nbG, 256>>>(x, 128, W1, 0);                  // main stream, concurrent
        cudaEventRecord(evJoin, s2);
        cudaStreamWaitEvent(0, evJoin, 0);
    } else {
        fill_kernel<<<nbE4, 256>>>(src4, dst4);                    // serial fallback
        gemm_kernel<<<nbG, 256>>>(x, 128, W1, 0);
    }

    agg_kernel<<<nbA, 256>>>(b1);
    colstats_kernel<<<256, 256>>>(gamma1, beta1);

    gemm_kernel<<<nbG, 256>>>(nullptr, 64, W2, 1);
    agg_kernel<<<nbA, 256>>>(b2);

    pool_kernel<<<GG, 256>>>();
    mlp_kernel<<<GG, 128>>>(gamma2, beta2, fW1, fb1, fW2, fb2,
                            fW3, fb3, fW4, fb4, oW, ob, out);
}